// round 2
// baseline (speedup 1.0000x reference)
#include <cuda_runtime.h>
#include <cstdint>
#include <cstddef>

#define NN   50000
#define NE   600000
#define NG   64
#define HID  128
#define OUTD 256

// ---------------- scratch (no allocation allowed) ----------------
__device__ float g_h[(size_t)NN * HID];
__device__ float g_coord[NN * 3];
__device__ float g_deg[NN];
__device__ float g_magg[(size_t)NN * HID];
__device__ float g_cagg[NN * 3];
__device__ float g_pool[NG * HID];
__device__ float g_cnt[NG];

__device__ __forceinline__ float silu_f(float x) { return x / (1.0f + __expf(-x)); }

// ---------------- 64-row x 128-col tiled GEMM core ----------------
// 256 threads, thread (tr=tid>>5, tc=tid&31) owns rows tr*8..tr*8+7, cols tc*4..tc*4+3.
// Input tile resident in smem (ldi stride, multiple of 4); weights streamed in 32x128 chunks.
__device__ __forceinline__ void gemm_tile64(
    const float* __restrict__ sIn, int ldi,
    const float* __restrict__ gW, int K,
    float* __restrict__ sW, float acc[8][4])
{
    const int tid = threadIdx.x;
    const int tr  = tid >> 5;
    const int tc  = tid & 31;

#pragma unroll
    for (int i = 0; i < 8; i++)
#pragma unroll
        for (int j = 0; j < 4; j++) acc[i][j] = 0.0f;

    int k0 = 0;
    for (; k0 + 32 <= K; k0 += 32) {
        __syncthreads();   // protect previous use of sW
#pragma unroll
        for (int j = 0; j < 4; j++) {
            int f  = tid + j * 256;
            int rw = f >> 5, cf = f & 31;
            *(float4*)&sW[rw * 128 + cf * 4] =
                __ldg(reinterpret_cast<const float4*>(&gW[(size_t)(k0 + rw) * 128 + cf * 4]));
        }
        __syncthreads();
#pragma unroll
        for (int k4 = 0; k4 < 32; k4 += 4) {
            float4 a[8];
#pragma unroll
            for (int i = 0; i < 8; i++)
                a[i] = *(const float4*)&sIn[(tr * 8 + i) * ldi + k0 + k4];
#pragma unroll
            for (int kk = 0; kk < 4; kk++) {
                float4 w = *(const float4*)&sW[(k4 + kk) * 128 + tc * 4];
#pragma unroll
                for (int i = 0; i < 8; i++) {
                    float av = (kk == 0) ? a[i].x : (kk == 1) ? a[i].y : (kk == 2) ? a[i].z : a[i].w;
                    acc[i][0] = fmaf(av, w.x, acc[i][0]);
                    acc[i][1] = fmaf(av, w.y, acc[i][1]);
                    acc[i][2] = fmaf(av, w.z, acc[i][2]);
                    acc[i][3] = fmaf(av, w.w, acc[i][3]);
                }
            }
        }
    }
    if (k0 < K) {              // K=258 tail (2 rows)
        int rem = K - k0;
        __syncthreads();
        for (int f = tid; f < rem * 32; f += 256) {
            int rw = f >> 5, cf = f & 31;
            *(float4*)&sW[rw * 128 + cf * 4] =
                __ldg(reinterpret_cast<const float4*>(&gW[(size_t)(k0 + rw) * 128 + cf * 4]));
        }
        __syncthreads();
        for (int k = 0; k < rem; k++) {
            float4 w = *(const float4*)&sW[k * 128 + tc * 4];
#pragma unroll
            for (int i = 0; i < 8; i++) {
                float av = sIn[(tr * 8 + i) * ldi + k0 + k];
                acc[i][0] = fmaf(av, w.x, acc[i][0]);
                acc[i][1] = fmaf(av, w.y, acc[i][1]);
                acc[i][2] = fmaf(av, w.z, acc[i][2]);
                acc[i][3] = fmaf(av, w.w, acc[i][3]);
            }
        }
    }
}

// ---------------- small utility kernels ----------------
__global__ void init_zero_kernel() {
    size_t idx = (size_t)blockIdx.x * 256 + threadIdx.x;
    if (idx < NN)        g_deg[idx]  = 0.0f;
    if (idx < NG * HID)  g_pool[idx] = 0.0f;
    if (idx < NG)        g_cnt[idx]  = 0.0f;
}

__global__ void zero_layer_kernel() {
    size_t idx = (size_t)blockIdx.x * 256 + threadIdx.x;
    if (idx < (size_t)NN * HID) g_magg[idx] = 0.0f;
    if (idx < NN * 3)           g_cagg[idx] = 0.0f;
}

__global__ void deg_kernel(const int* __restrict__ erow) {
    int e = blockIdx.x * 256 + threadIdx.x;
    if (e < NE) atomicAdd(&g_deg[erow[e]], 1.0f);
}

__global__ void cnt_kernel(const int* __restrict__ batch) {
    int i = blockIdx.x * 256 + threadIdx.x;
    if (i < NN) atomicAdd(&g_cnt[batch[i]], 1.0f);
}

__global__ void copy_coord_kernel(const float* __restrict__ c) {
    int i = blockIdx.x * 256 + threadIdx.x;
    if (i < NN * 3) g_coord[i] = c[i];
}

// h = x @ emb_in_w + b   (K=16)
__global__ void embed_kernel(const float* __restrict__ x,
                             const float* __restrict__ W,
                             const float* __restrict__ b) {
    size_t idx = (size_t)blockIdx.x * 256 + threadIdx.x;
    if (idx >= (size_t)NN * HID) return;
    int i = (int)(idx >> 7);
    int c = (int)(idx & 127);
    const float* xr = &x[i * 16];
    float a = b[c];
#pragma unroll
    for (int k = 0; k < 16; k++) a = fmaf(xr[k], W[k * 128 + c], a);
    g_h[idx] = a;
}

// ---------------- edge pipeline (the hot kernel) ----------------
// smem floats: sEF 64*260 | sA 64*132 | sB 64*132 | sW 32*128 | sD 64*4
#define EDGE_SMEM_F (64 * 260 + 64 * 132 + 64 * 132 + 32 * 128 + 64 * 4)

__global__ void __launch_bounds__(256) edge_kernel(
    const int* __restrict__ erow, const int* __restrict__ ecol,
    const float* __restrict__ eattr,
    const float* __restrict__ W1, const float* __restrict__ b1,
    const float* __restrict__ W2, const float* __restrict__ b2,
    const float* __restrict__ Wc1, const float* __restrict__ bc1,
    const float* __restrict__ Wc2)
{
    extern __shared__ float sm[];
    float* sEF = sm;                    // 64 x 260 : [h_row | h_col | radial | eattr | 0 0]
    float* sA  = sEF + 64 * 260;        // 64 x 132
    float* sB  = sA + 64 * 132;         // 64 x 132
    float* sW  = sB + 64 * 132;         // 32 x 128
    float* sD  = sW + 32 * 128;         // 64 x 4 (diff xyz)
    __shared__ int sRow[64];

    const int tid = threadIdx.x;
    const int warp = tid >> 5, lane = tid & 31;
    const int e0 = blockIdx.x * 64;

    // gather
    for (int i = warp; i < 64; i += 8) {
        int e = e0 + i;
        int r = erow[e], c = ecol[e];
        if (lane == 0) sRow[i] = r;
        ((float4*)&sEF[i * 260])[lane] =
            __ldg(reinterpret_cast<const float4*>(&g_h[(size_t)r * 128 + lane * 4]));
        ((float4*)&sEF[i * 260 + 128])[lane] =
            __ldg(reinterpret_cast<const float4*>(&g_h[(size_t)c * 128 + lane * 4]));
        if (lane < 3) sD[i * 4 + lane] = g_coord[r * 3 + lane] - g_coord[c * 3 + lane];
        __syncwarp();
        if (lane == 0) {
            float d0 = sD[i * 4], d1 = sD[i * 4 + 1], d2 = sD[i * 4 + 2];
            sEF[i * 260 + 256] = d0 * d0 + d1 * d1 + d2 * d2;
            sEF[i * 260 + 257] = eattr[e];
            sEF[i * 260 + 258] = 0.0f;
            sEF[i * 260 + 259] = 0.0f;
        }
    }

    const int tr = tid >> 5, tc = tid & 31;
    float acc[8][4];

    // GEMM1: m1 = silu(ef @ W1 + b1), K = 258
    gemm_tile64(sEF, 260, W1, 258, sW, acc);
    {
        float4 bb = *(const float4*)&b1[tc * 4];
#pragma unroll
        for (int i = 0; i < 8; i++) {
            float4 v;
            v.x = silu_f(acc[i][0] + bb.x);
            v.y = silu_f(acc[i][1] + bb.y);
            v.z = silu_f(acc[i][2] + bb.z);
            v.w = silu_f(acc[i][3] + bb.w);
            *(float4*)&sA[(tr * 8 + i) * 132 + tc * 4] = v;
        }
    }
    __syncthreads();

    // GEMM2: m = silu(m1 @ W2 + b2), K = 128 ; scatter magg in epilogue
    gemm_tile64(sA, 132, W2, 128, sW, acc);
    {
        float4 bb = *(const float4*)&b2[tc * 4];
#pragma unroll
        for (int i = 0; i < 8; i++) {
            int node = sRow[tr * 8 + i];
            float4 v;
            v.x = silu_f(acc[i][0] + bb.x);
            v.y = silu_f(acc[i][1] + bb.y);
            v.z = silu_f(acc[i][2] + bb.z);
            v.w = silu_f(acc[i][3] + bb.w);
            *(float4*)&sB[(tr * 8 + i) * 132 + tc * 4] = v;
            float* mg = &g_magg[(size_t)node * 128 + tc * 4];
            atomicAdd(mg + 0, v.x);
            atomicAdd(mg + 1, v.y);
            atomicAdd(mg + 2, v.z);
            atomicAdd(mg + 3, v.w);
        }
    }
    __syncthreads();

    // GEMM3: p = silu(m @ Wc1 + bc1); cw = p @ Wc2 ; scatter coord agg
    gemm_tile64(sB, 132, Wc1, 128, sW, acc);
    {
        float4 bb = *(const float4*)&bc1[tc * 4];
        float4 wc = *(const float4*)&Wc2[tc * 4];
#pragma unroll
        for (int i = 0; i < 8; i++) {
            float p0 = silu_f(acc[i][0] + bb.x);
            float p1 = silu_f(acc[i][1] + bb.y);
            float p2 = silu_f(acc[i][2] + bb.z);
            float p3 = silu_f(acc[i][3] + bb.w);
            float part = p0 * wc.x + p1 * wc.y + p2 * wc.z + p3 * wc.w;
#pragma unroll
            for (int o = 16; o > 0; o >>= 1) part += __shfl_xor_sync(0xffffffffu, part, o);
            if (lane == 0) {
                int row  = tr * 8 + i;
                int node = sRow[row];
                atomicAdd(&g_cagg[node * 3 + 0], sD[row * 4 + 0] * part);
                atomicAdd(&g_cagg[node * 3 + 1], sD[row * 4 + 1] * part);
                atomicAdd(&g_cagg[node * 3 + 2], sD[row * 4 + 2] * part);
            }
        }
    }
}

// ---------------- node update ----------------
// smem floats: sNF 64*260 | sA 64*132 | sW 32*128
#define NODE_SMEM_F (64 * 260 + 64 * 132 + 32 * 128)

__global__ void __launch_bounds__(256) node_kernel(
    const float* __restrict__ W1, const float* __restrict__ b1,
    const float* __restrict__ W2, const float* __restrict__ b2)
{
    extern __shared__ float sm[];
    float* sNF = sm;                 // 64 x 260 : [h | magg]
    float* sA  = sNF + 64 * 260;     // 64 x 132
    float* sW  = sA + 64 * 132;      // 32 x 128

    const int tid = threadIdx.x;
    const int warp = tid >> 5, lane = tid & 31;
    const int n0 = blockIdx.x * 64;

    // coord += cagg / deg
    if (tid < 192) {
        int i = tid / 3, d = tid - i * 3;
        int node = n0 + i;
        if (node < NN)
            g_coord[node * 3 + d] += g_cagg[node * 3 + d] / fmaxf(g_deg[node], 1.0f);
    }

    for (int i = warp; i < 64; i += 8) {
        int node = n0 + i;
        if (node < NN) {
            ((float4*)&sNF[i * 260])[lane] =
                *(const float4*)&g_h[(size_t)node * 128 + lane * 4];
            ((float4*)&sNF[i * 260 + 128])[lane] =
                *(const float4*)&g_magg[(size_t)node * 128 + lane * 4];
        } else {
            ((float4*)&sNF[i * 260])[lane]       = make_float4(0.f, 0.f, 0.f, 0.f);
            ((float4*)&sNF[i * 260 + 128])[lane] = make_float4(0.f, 0.f, 0.f, 0.f);
        }
    }

    const int tr = tid >> 5, tc = tid & 31;
    float acc[8][4];

    gemm_tile64(sNF, 260, W1, 256, sW, acc);
    {
        float4 bb = *(const float4*)&b1[tc * 4];
#pragma unroll
        for (int i = 0; i < 8; i++) {
            float4 v;
            v.x = silu_f(acc[i][0] + bb.x);
            v.y = silu_f(acc[i][1] + bb.y);
            v.z = silu_f(acc[i][2] + bb.z);
            v.w = silu_f(acc[i][3] + bb.w);
            *(float4*)&sA[(tr * 8 + i) * 132 + tc * 4] = v;
        }
    }
    __syncthreads();

    gemm_tile64(sA, 132, W2, 128, sW, acc);
    {
        float4 bb = *(const float4*)&b2[tc * 4];
#pragma unroll
        for (int i = 0; i < 8; i++) {
            int node = n0 + tr * 8 + i;
            if (node < NN) {
                float4 hv = *(const float4*)&sNF[(tr * 8 + i) * 260 + tc * 4];
                float4 o;
                o.x = hv.x + acc[i][0] + bb.x;
                o.y = hv.y + acc[i][1] + bb.y;
                o.z = hv.z + acc[i][2] + bb.z;
                o.w = hv.w + acc[i][3] + bb.w;
                *(float4*)&g_h[(size_t)node * 128 + tc * 4] = o;
            }
        }
    }
}

// ---------------- emb_out + graph pooling ----------------
// smem floats: sH 64*132 | sW 32*128
#define POOL_SMEM_F (64 * 132 + 32 * 128)

__global__ void __launch_bounds__(256) embpool_kernel(
    const int* __restrict__ batch,
    const float* __restrict__ W, const float* __restrict__ b)
{
    extern __shared__ float sm[];
    float* sH = sm;                 // 64 x 132
    float* sW = sH + 64 * 132;      // 32 x 128

    const int tid = threadIdx.x;
    const int warp = tid >> 5, lane = tid & 31;
    const int n0 = blockIdx.x * 64;

    for (int i = warp; i < 64; i += 8) {
        int node = n0 + i;
        ((float4*)&sH[i * 132])[lane] = (node < NN)
            ? *(const float4*)&g_h[(size_t)node * 128 + lane * 4]
            : make_float4(0.f, 0.f, 0.f, 0.f);
    }

    const int tr = tid >> 5, tc = tid & 31;
    float acc[8][4];
    gemm_tile64(sH, 132, W, 128, sW, acc);

    float4 bb = *(const float4*)&b[tc * 4];
#pragma unroll
    for (int i = 0; i < 8; i++) {
        int node = n0 + tr * 8 + i;
        if (node < NN) {
            int g = batch[node];
            float* pp = &g_pool[g * 128 + tc * 4];
            atomicAdd(pp + 0, acc[i][0] + bb.x);
            atomicAdd(pp + 1, acc[i][1] + bb.y);
            atomicAdd(pp + 2, acc[i][2] + bb.z);
            atomicAdd(pp + 3, acc[i][3] + bb.w);
        }
    }
}

// ---------------- final FC over pooled graph features ----------------
__global__ void final_kernel(const float* __restrict__ fcW,
                             const float* __restrict__ fcB,
                             float* __restrict__ out)
{
    __shared__ float sg[128];
    int c = threadIdx.x;          // 0..255
    for (int g = 0; g < NG; g++) {
        if (c < 128) sg[c] = g_pool[g * 128 + c] / fmaxf(g_cnt[g], 1.0f);
        __syncthreads();
        float a = fcB[c];
#pragma unroll 8
        for (int k = 0; k < 128; k++) a = fmaf(sg[k], fcW[k * 256 + c], a);
        out[g * 256 + c] = a;
        __syncthreads();
    }
}

// ---------------- launch ----------------
extern "C" void kernel_launch(void* const* d_in, const int* in_sizes, int n_in,
                              void* d_out, int out_size)
{
    const float* x        = (const float*)d_in[0];
    const int*   eidx     = (const int*)d_in[1];
    const float* coord_in = (const float*)d_in[2];
    const float* eattr    = (const float*)d_in[3];
    const int*   batch    = (const int*)d_in[4];
    const float* emb_in_w = (const float*)d_in[5];
    const float* emb_in_b = (const float*)d_in[6];
    const float* edge_w1  = (const float*)d_in[7];
    const float* edge_b1  = (const float*)d_in[8];
    const float* edge_w2  = (const float*)d_in[9];
    const float* edge_b2  = (const float*)d_in[10];
    const float* node_w1  = (const float*)d_in[11];
    const float* node_b1  = (const float*)d_in[12];
    const float* node_w2  = (const float*)d_in[13];
    const float* node_b2  = (const float*)d_in[14];
    const float* coord_w1 = (const float*)d_in[15];
    const float* coord_b1 = (const float*)d_in[16];
    const float* coord_w2 = (const float*)d_in[17];
    const float* emb_out_w= (const float*)d_in[18];
    const float* emb_out_b= (const float*)d_in[19];
    const float* fc_w     = (const float*)d_in[20];
    const float* fc_b     = (const float*)d_in[21];
    float* out = (float*)d_out;

    const int* erow = eidx;
    const int* ecol = eidx + NE;

    static bool attr_done = false;
    if (!attr_done) {
        cudaFuncSetAttribute(edge_kernel, cudaFuncAttributeMaxDynamicSharedMemorySize,
                             EDGE_SMEM_F * 4);
        cudaFuncSetAttribute(node_kernel, cudaFuncAttributeMaxDynamicSharedMemorySize,
                             NODE_SMEM_F * 4);
        cudaFuncSetAttribute(embpool_kernel, cudaFuncAttributeMaxDynamicSharedMemorySize,
                             POOL_SMEM_F * 4);
        attr_done = true;
    }

    init_zero_kernel<<<(NN + 255) / 256, 256>>>();
    deg_kernel<<<(NE + 255) / 256, 256>>>(erow);
    embed_kernel<<<((size_t)NN * HID + 255) / 256, 256>>>(x, emb_in_w, emb_in_b);
    copy_coord_kernel<<<(NN * 3 + 255) / 256, 256>>>(coord_in);

    const int edge_blocks = NE / 64;              // 9375, exact
    const int node_blocks = (NN + 63) / 64;       // 782

    for (int l = 0; l < 3; l++) {
        zero_layer_kernel<<<((size_t)NN * HID + 255) / 256, 256>>>();
        edge_kernel<<<edge_blocks, 256, EDGE_SMEM_F * 4>>>(
            erow, ecol, eattr,
            edge_w1 + (size_t)l * 258 * 128, edge_b1 + l * 128,
            edge_w2 + (size_t)l * 128 * 128, edge_b2 + l * 128,
            coord_w1 + (size_t)l * 128 * 128, coord_b1 + l * 128,
            coord_w2 + (size_t)l * 128);
        node_kernel<<<node_blocks, 256, NODE_SMEM_F * 4>>>(
            node_w1 + (size_t)l * 256 * 128, node_b1 + l * 128,
            node_w2 + (size_t)l * 128 * 128, node_b2 + l * 128);
    }

    cnt_kernel<<<(NN + 255) / 256, 256>>>(batch);
    embpool_kernel<<<node_blocks, 256, POOL_SMEM_F * 4>>>(batch, emb_out_w, emb_out_b);
    final_kernel<<<1, 256>>>(fc_w, fc_b, out);
}

// round 3
// speedup vs baseline: 1.8056x; 1.8056x over previous
#include <cuda_runtime.h>
#include <cstdint>
#include <cstddef>

#define NN   50000
#define NE   600000
#define NG   64
#define HID  128
#define OUTD 256

// ---------------- scratch (no allocation allowed) ----------------
__device__ float g_h[(size_t)NN * HID];
__device__ float g_hr[(size_t)NN * HID];   // h @ W1a  (per-layer)
__device__ float g_hc[(size_t)NN * HID];   // h @ W1b
__device__ float g_coord[NN * 3];
__device__ float g_deg[NN];
__device__ float g_magg[(size_t)NN * HID];
__device__ float g_cagg[NN * 3];
__device__ float g_pool[NG * HID];
__device__ float g_cnt[NG];

__device__ __forceinline__ float silu_f(float x) { return x / (1.0f + __expf(-x)); }

// ---------------- 64-row x 128-col tiled GEMM core ----------------
// 256 threads; thread (tr=tid>>5, tc=tid&31) owns rows tr*8..+7, cols tc*4..+3.
__device__ __forceinline__ void gemm_tile64(
    const float* __restrict__ sIn, int ldi,
    const float* __restrict__ gW, int K,
    float* __restrict__ sW, float acc[8][4])
{
    const int tid = threadIdx.x;
    const int tr  = tid >> 5;
    const int tc  = tid & 31;

#pragma unroll
    for (int i = 0; i < 8; i++)
#pragma unroll
        for (int j = 0; j < 4; j++) acc[i][j] = 0.0f;

    for (int k0 = 0; k0 + 32 <= K; k0 += 32) {
        __syncthreads();   // protect previous use of sW
#pragma unroll
        for (int j = 0; j < 4; j++) {
            int f  = tid + j * 256;
            int rw = f >> 5, cf = f & 31;
            *(float4*)&sW[rw * 128 + cf * 4] =
                __ldg(reinterpret_cast<const float4*>(&gW[(size_t)(k0 + rw) * 128 + cf * 4]));
        }
        __syncthreads();
#pragma unroll
        for (int k4 = 0; k4 < 32; k4 += 4) {
            float4 a[8];
#pragma unroll
            for (int i = 0; i < 8; i++)
                a[i] = *(const float4*)&sIn[(tr * 8 + i) * ldi + k0 + k4];
#pragma unroll
            for (int kk = 0; kk < 4; kk++) {
                float4 w = *(const float4*)&sW[(k4 + kk) * 128 + tc * 4];
#pragma unroll
                for (int i = 0; i < 8; i++) {
                    float av = (kk == 0) ? a[i].x : (kk == 1) ? a[i].y : (kk == 2) ? a[i].z : a[i].w;
                    acc[i][0] = fmaf(av, w.x, acc[i][0]);
                    acc[i][1] = fmaf(av, w.y, acc[i][1]);
                    acc[i][2] = fmaf(av, w.z, acc[i][2]);
                    acc[i][3] = fmaf(av, w.w, acc[i][3]);
                }
            }
        }
    }
}

// ---------------- small utility kernels ----------------
__global__ void init_zero_kernel() {
    size_t idx = (size_t)blockIdx.x * 256 + threadIdx.x;
    if (idx < NN)        g_deg[idx]  = 0.0f;
    if (idx < NG * HID)  g_pool[idx] = 0.0f;
    if (idx < NG)        g_cnt[idx]  = 0.0f;
}

__global__ void zero_layer_kernel() {
    size_t idx = (size_t)blockIdx.x * 256 + threadIdx.x;
    if (idx < (size_t)NN * HID) g_magg[idx] = 0.0f;
    if (idx < NN * 3)           g_cagg[idx] = 0.0f;
}

__global__ void deg_kernel(const int* __restrict__ erow) {
    int e = blockIdx.x * 256 + threadIdx.x;
    if (e < NE) atomicAdd(&g_deg[erow[e]], 1.0f);
}

__global__ void cnt_kernel(const int* __restrict__ batch) {
    int i = blockIdx.x * 256 + threadIdx.x;
    if (i < NN) atomicAdd(&g_cnt[batch[i]], 1.0f);
}

__global__ void copy_coord_kernel(const float* __restrict__ c) {
    int i = blockIdx.x * 256 + threadIdx.x;
    if (i < NN * 3) g_coord[i] = c[i];
}

// h = x @ emb_in_w + b   (K=16)
__global__ void embed_kernel(const float* __restrict__ x,
                             const float* __restrict__ W,
                             const float* __restrict__ b) {
    size_t idx = (size_t)blockIdx.x * 256 + threadIdx.x;
    if (idx >= (size_t)NN * HID) return;
    int i = (int)(idx >> 7);
    int c = (int)(idx & 127);
    const float* xr = &x[i * 16];
    float a = b[c];
#pragma unroll
    for (int k = 0; k < 16; k++) a = fmaf(xr[k], W[k * 128 + c], a);
    g_h[idx] = a;
}

// ---------------- per-node precompute: g_hr = h@W1a, g_hc = h@W1b ----------------
// smem floats: sH 64*132 | sW 32*128
#define HPRE_SMEM_F (64 * 132 + 32 * 128)

__global__ void __launch_bounds__(256) hpre_kernel(const float* __restrict__ W1)
{
    extern __shared__ float sm[];
    float* sH = sm;
    float* sW = sH + 64 * 132;

    const int tid = threadIdx.x;
    const int warp = tid >> 5, lane = tid & 31;
    const int n0 = blockIdx.x * 64;

    for (int i = warp; i < 64; i += 8) {
        int node = n0 + i;
        ((float4*)&sH[i * 132])[lane] = (node < NN)
            ? *(const float4*)&g_h[(size_t)node * 128 + lane * 4]
            : make_float4(0.f, 0.f, 0.f, 0.f);
    }

    const int tr = tid >> 5, tc = tid & 31;
    float acc[8][4];

    gemm_tile64(sH, 132, W1, 128, sW, acc);                 // W1a = rows 0..127
#pragma unroll
    for (int i = 0; i < 8; i++) {
        int node = n0 + tr * 8 + i;
        if (node < NN)
            *(float4*)&g_hr[(size_t)node * 128 + tc * 4] =
                make_float4(acc[i][0], acc[i][1], acc[i][2], acc[i][3]);
    }
    __syncthreads();

    gemm_tile64(sH, 132, W1 + 128 * 128, 128, sW, acc);     // W1b = rows 128..255
#pragma unroll
    for (int i = 0; i < 8; i++) {
        int node = n0 + tr * 8 + i;
        if (node < NN)
            *(float4*)&g_hc[(size_t)node * 128 + tc * 4] =
                make_float4(acc[i][0], acc[i][1], acc[i][2], acc[i][3]);
    }
}

// ---------------- edge pipeline (the hot kernel) ----------------
// m1 = silu(hr[row] + hc[col] + radial*w_r + ea*w_e + b1)  -- no K=258 GEMM
// smem floats: sA 64*132 | sB 64*132 | sW 32*128 | sD 64*4 | wr/we/b1 3*128
#define EDGE_SMEM_F (64 * 132 * 2 + 32 * 128 + 64 * 4 + 3 * 128)

__global__ void __launch_bounds__(256) edge_kernel(
    const int* __restrict__ erow, const int* __restrict__ ecol,
    const float* __restrict__ eattr,
    const float* __restrict__ W1, const float* __restrict__ b1,
    const float* __restrict__ W2, const float* __restrict__ b2,
    const float* __restrict__ Wc1, const float* __restrict__ bc1,
    const float* __restrict__ Wc2)
{
    extern __shared__ float sm[];
    float* sA  = sm;                    // 64 x 132
    float* sB  = sA + 64 * 132;         // 64 x 132
    float* sW  = sB + 64 * 132;         // 32 x 128
    float* sD  = sW + 32 * 128;         // 64 x 4 (diff xyz)
    float* sWR = sD + 64 * 4;           // 128
    float* sWE = sWR + 128;             // 128
    float* sB1 = sWE + 128;             // 128
    __shared__ int sRow[64];

    const int tid = threadIdx.x;
    const int warp = tid >> 5, lane = tid & 31;
    const int e0 = blockIdx.x * 64;

    if (tid < 128) {
        sWR[tid] = __ldg(&W1[256 * 128 + tid]);   // radial row
        sWE[tid] = __ldg(&W1[257 * 128 + tid]);   // edge_attr row
        sB1[tid] = __ldg(&b1[tid]);
    }
    __syncthreads();

    // gather + fused first-layer MLP input
    for (int i = warp; i < 64; i += 8) {
        int e = e0 + i;
        int r = erow[e], c = ecol[e];
        if (lane == 0) sRow[i] = r;
        float d = 0.0f;
        if (lane < 3) { d = g_coord[r * 3 + lane] - g_coord[c * 3 + lane]; sD[i * 4 + lane] = d; }
        __syncwarp();
        float d0 = sD[i * 4], d1 = sD[i * 4 + 1], d2 = sD[i * 4 + 2];
        float radial = d0 * d0 + d1 * d1 + d2 * d2;
        float ea = __ldg(&eattr[e]);
        float4 a = __ldg(reinterpret_cast<const float4*>(&g_hr[(size_t)r * 128 + lane * 4]));
        float4 b = __ldg(reinterpret_cast<const float4*>(&g_hc[(size_t)c * 128 + lane * 4]));
        float4 wr = *(const float4*)&sWR[lane * 4];
        float4 we = *(const float4*)&sWE[lane * 4];
        float4 bb = *(const float4*)&sB1[lane * 4];
        float4 v;
        v.x = silu_f(a.x + b.x + radial * wr.x + ea * we.x + bb.x);
        v.y = silu_f(a.y + b.y + radial * wr.y + ea * we.y + bb.y);
        v.z = silu_f(a.z + b.z + radial * wr.z + ea * we.z + bb.z);
        v.w = silu_f(a.w + b.w + radial * wr.w + ea * we.w + bb.w);
        *(float4*)&sA[i * 132 + lane * 4] = v;
    }

    const int tr = tid >> 5, tc = tid & 31;
    float acc[8][4];

    // GEMM2: m = silu(m1 @ W2 + b2), K = 128 ; scatter magg in epilogue
    gemm_tile64(sA, 132, W2, 128, sW, acc);
    {
        float4 bb = *(const float4*)&b2[tc * 4];
#pragma unroll
        for (int i = 0; i < 8; i++) {
            int node = sRow[tr * 8 + i];
            float4 v;
            v.x = silu_f(acc[i][0] + bb.x);
            v.y = silu_f(acc[i][1] + bb.y);
            v.z = silu_f(acc[i][2] + bb.z);
            v.w = silu_f(acc[i][3] + bb.w);
            *(float4*)&sB[(tr * 8 + i) * 132 + tc * 4] = v;
            float* mg = &g_magg[(size_t)node * 128 + tc * 4];
            atomicAdd(mg + 0, v.x);
            atomicAdd(mg + 1, v.y);
            atomicAdd(mg + 2, v.z);
            atomicAdd(mg + 3, v.w);
        }
    }
    __syncthreads();

    // GEMM3: p = silu(m @ Wc1 + bc1); cw = p @ Wc2 ; scatter coord agg
    gemm_tile64(sB, 132, Wc1, 128, sW, acc);
    {
        float4 bb = *(const float4*)&bc1[tc * 4];
        float4 wc = *(const float4*)&Wc2[tc * 4];
#pragma unroll
        for (int i = 0; i < 8; i++) {
            float p0 = silu_f(acc[i][0] + bb.x);
            float p1 = silu_f(acc[i][1] + bb.y);
            float p2 = silu_f(acc[i][2] + bb.z);
            float p3 = silu_f(acc[i][3] + bb.w);
            float part = p0 * wc.x + p1 * wc.y + p2 * wc.z + p3 * wc.w;
#pragma unroll
            for (int o = 16; o > 0; o >>= 1) part += __shfl_xor_sync(0xffffffffu, part, o);
            if (lane == 0) {
                int row  = tr * 8 + i;
                int node = sRow[row];
                atomicAdd(&g_cagg[node * 3 + 0], sD[row * 4 + 0] * part);
                atomicAdd(&g_cagg[node * 3 + 1], sD[row * 4 + 1] * part);
                atomicAdd(&g_cagg[node * 3 + 2], sD[row * 4 + 2] * part);
            }
        }
    }
}

// ---------------- node update ----------------
// smem floats: sNF 64*260 | sA 64*132 | sW 32*128
#define NODE_SMEM_F (64 * 260 + 64 * 132 + 32 * 128)

__global__ void __launch_bounds__(256) node_kernel(
    const float* __restrict__ W1, const float* __restrict__ b1,
    const float* __restrict__ W2, const float* __restrict__ b2)
{
    extern __shared__ float sm[];
    float* sNF = sm;                 // 64 x 260 : [h | magg]
    float* sA  = sNF + 64 * 260;     // 64 x 132
    float* sW  = sA + 64 * 132;      // 32 x 128

    const int tid = threadIdx.x;
    const int warp = tid >> 5, lane = tid & 31;
    const int n0 = blockIdx.x * 64;

    // coord += cagg / deg
    if (tid < 192) {
        int i = tid / 3, d = tid - i * 3;
        int node = n0 + i;
        if (node < NN)
            g_coord[node * 3 + d] += g_cagg[node * 3 + d] / fmaxf(g_deg[node], 1.0f);
    }

    for (int i = warp; i < 64; i += 8) {
        int node = n0 + i;
        if (node < NN) {
            ((float4*)&sNF[i * 260])[lane] =
                *(const float4*)&g_h[(size_t)node * 128 + lane * 4];
            ((float4*)&sNF[i * 260 + 128])[lane] =
                *(const float4*)&g_magg[(size_t)node * 128 + lane * 4];
        } else {
            ((float4*)&sNF[i * 260])[lane]       = make_float4(0.f, 0.f, 0.f, 0.f);
            ((float4*)&sNF[i * 260 + 128])[lane] = make_float4(0.f, 0.f, 0.f, 0.f);
        }
    }

    const int tr = tid >> 5, tc = tid & 31;
    float acc[8][4];

    gemm_tile64(sNF, 260, W1, 256, sW, acc);
    {
        float4 bb = *(const float4*)&b1[tc * 4];
#pragma unroll
        for (int i = 0; i < 8; i++) {
            float4 v;
            v.x = silu_f(acc[i][0] + bb.x);
            v.y = silu_f(acc[i][1] + bb.y);
            v.z = silu_f(acc[i][2] + bb.z);
            v.w = silu_f(acc[i][3] + bb.w);
            *(float4*)&sA[(tr * 8 + i) * 132 + tc * 4] = v;
        }
    }
    __syncthreads();

    gemm_tile64(sA, 132, W2, 128, sW, acc);
    {
        float4 bb = *(const float4*)&b2[tc * 4];
#pragma unroll
        for (int i = 0; i < 8; i++) {
            int node = n0 + tr * 8 + i;
            if (node < NN) {
                float4 hv = *(const float4*)&sNF[(tr * 8 + i) * 260 + tc * 4];
                float4 o;
                o.x = hv.x + acc[i][0] + bb.x;
                o.y = hv.y + acc[i][1] + bb.y;
                o.z = hv.z + acc[i][2] + bb.z;
                o.w = hv.w + acc[i][3] + bb.w;
                *(float4*)&g_h[(size_t)node * 128 + tc * 4] = o;
            }
        }
    }
}

// ---------------- emb_out + graph pooling ----------------
#define POOL_SMEM_F (64 * 132 + 32 * 128)

__global__ void __launch_bounds__(256) embpool_kernel(
    const int* __restrict__ batch,
    const float* __restrict__ W, const float* __restrict__ b)
{
    extern __shared__ float sm[];
    float* sH = sm;
    float* sW = sH + 64 * 132;

    const int tid = threadIdx.x;
    const int warp = tid >> 5, lane = tid & 31;
    const int n0 = blockIdx.x * 64;

    for (int i = warp; i < 64; i += 8) {
        int node = n0 + i;
        ((float4*)&sH[i * 132])[lane] = (node < NN)
            ? *(const float4*)&g_h[(size_t)node * 128 + lane * 4]
            : make_float4(0.f, 0.f, 0.f, 0.f);
    }

    const int tr = tid >> 5, tc = tid & 31;
    float acc[8][4];
    gemm_tile64(sH, 132, W, 128, sW, acc);

    float4 bb = *(const float4*)&b[tc * 4];
#pragma unroll
    for (int i = 0; i < 8; i++) {
        int node = n0 + tr * 8 + i;
        if (node < NN) {
            int g = batch[node];
            float* pp = &g_pool[g * 128 + tc * 4];
            atomicAdd(pp + 0, acc[i][0] + bb.x);
            atomicAdd(pp + 1, acc[i][1] + bb.y);
            atomicAdd(pp + 2, acc[i][2] + bb.z);
            atomicAdd(pp + 3, acc[i][3] + bb.w);
        }
    }
}

// ---------------- final FC over pooled graph features ----------------
__global__ void final_kernel(const float* __restrict__ fcW,
                             const float* __restrict__ fcB,
                             float* __restrict__ out)
{
    __shared__ float sg[128];
    int c = threadIdx.x;
    for (int g = 0; g < NG; g++) {
        if (c < 128) sg[c] = g_pool[g * 128 + c] / fmaxf(g_cnt[g], 1.0f);
        __syncthreads();
        float a = fcB[c];
#pragma unroll 8
        for (int k = 0; k < 128; k++) a = fmaf(sg[k], fcW[k * 256 + c], a);
        out[g * 256 + c] = a;
        __syncthreads();
    }
}

// ---------------- launch ----------------
extern "C" void kernel_launch(void* const* d_in, const int* in_sizes, int n_in,
                              void* d_out, int out_size)
{
    const float* x        = (const float*)d_in[0];
    const int*   eidx     = (const int*)d_in[1];
    const float* coord_in = (const float*)d_in[2];
    const float* eattr    = (const float*)d_in[3];
    const int*   batch    = (const int*)d_in[4];
    const float* emb_in_w = (const float*)d_in[5];
    const float* emb_in_b = (const float*)d_in[6];
    const float* edge_w1  = (const float*)d_in[7];
    const float* edge_b1  = (const float*)d_in[8];
    const float* edge_w2  = (const float*)d_in[9];
    const float* edge_b2  = (const float*)d_in[10];
    const float* node_w1  = (const float*)d_in[11];
    const float* node_b1  = (const float*)d_in[12];
    const float* node_w2  = (const float*)d_in[13];
    const float* node_b2  = (const float*)d_in[14];
    const float* coord_w1 = (const float*)d_in[15];
    const float* coord_b1 = (const float*)d_in[16];
    const float* coord_w2 = (const float*)d_in[17];
    const float* emb_out_w= (const float*)d_in[18];
    const float* emb_out_b= (const float*)d_in[19];
    const float* fc_w     = (const float*)d_in[20];
    const float* fc_b     = (const float*)d_in[21];
    float* out = (float*)d_out;

    const int* erow = eidx;
    const int* ecol = eidx + NE;

    static bool attr_done = false;
    if (!attr_done) {
        cudaFuncSetAttribute(edge_kernel, cudaFuncAttributeMaxDynamicSharedMemorySize,
                             EDGE_SMEM_F * 4);
        cudaFuncSetAttribute(node_kernel, cudaFuncAttributeMaxDynamicSharedMemorySize,
                             NODE_SMEM_F * 4);
        cudaFuncSetAttribute(embpool_kernel, cudaFuncAttributeMaxDynamicSharedMemorySize,
                             POOL_SMEM_F * 4);
        cudaFuncSetAttribute(hpre_kernel, cudaFuncAttributeMaxDynamicSharedMemorySize,
                             HPRE_SMEM_F * 4);
        attr_done = true;
    }

    init_zero_kernel<<<(NN + 255) / 256, 256>>>();
    deg_kernel<<<(NE + 255) / 256, 256>>>(erow);
    embed_kernel<<<((size_t)NN * HID + 255) / 256, 256>>>(x, emb_in_w, emb_in_b);
    copy_coord_kernel<<<(NN * 3 + 255) / 256, 256>>>(coord_in);

    const int edge_blocks = NE / 64;              // 9375, exact
    const int node_blocks = (NN + 63) / 64;       // 782

    for (int l = 0; l < 3; l++) {
        zero_layer_kernel<<<((size_t)NN * HID + 255) / 256, 256>>>();
        hpre_kernel<<<node_blocks, 256, HPRE_SMEM_F * 4>>>(edge_w1 + (size_t)l * 258 * 128);
        edge_kernel<<<edge_blocks, 256, EDGE_SMEM_F * 4>>>(
            erow, ecol, eattr,
            edge_w1 + (size_t)l * 258 * 128, edge_b1 + l * 128,
            edge_w2 + (size_t)l * 128 * 128, edge_b2 + l * 128,
            coord_w1 + (size_t)l * 128 * 128, coord_b1 + l * 128,
            coord_w2 + (size_t)l * 128);
        node_kernel<<<node_blocks, 256, NODE_SMEM_F * 4>>>(
            node_w1 + (size_t)l * 256 * 128, node_b1 + l * 128,
            node_w2 + (size_t)l * 128 * 128, node_b2 + l * 128);
    }

    cnt_kernel<<<(NN + 255) / 256, 256>>>(batch);
    embpool_kernel<<<node_blocks, 256, POOL_SMEM_F * 4>>>(batch, emb_out_w, emb_out_b);
    final_kernel<<<1, 256>>>(fc_w, fc_b, out);
}

// round 5
// speedup vs baseline: 1.9394x; 1.0741x over previous
#include <cuda_runtime.h>
#include <cstdint>
#include <cstddef>

#define NN   50000
#define NE   600000
#define NG   64
#define HID  128
#define OUTD 256

// ---------------- scratch (no allocation allowed) ----------------
__device__ float g_h[(size_t)NN * HID];
__device__ float g_hr[(size_t)NN * HID];   // h @ W1a  (per-layer)
__device__ float g_hc[(size_t)NN * HID];   // h @ W1b
__device__ float g_coord[NN * 3];
__device__ float g_deg[NN];
__device__ float g_magg[(size_t)NN * HID];
__device__ float g_cagg[NN * 3];
__device__ float g_pool[NG * HID];
__device__ float g_cnt[NG];

__device__ __forceinline__ float silu_f(float x) { return x / (1.0f + __expf(-x)); }

// ---------------- packed f32x2 FMA (Blackwell FFMA2; PTX-only) ----------------
__device__ __forceinline__ void fma2(unsigned long long& d,
                                     unsigned long long a, unsigned long long b) {
    asm("fma.rn.f32x2 %0, %1, %2, %0;" : "+l"(d) : "l"(a), "l"(b));
}
__device__ __forceinline__ unsigned long long pack2(float x) {
    unsigned long long r;
    asm("mov.b64 %0, {%1, %1};" : "=l"(r) : "f"(x));
    return r;
}
__device__ __forceinline__ void unpack2(unsigned long long v, float& lo, float& hi) {
    asm("mov.b64 {%0, %1}, %2;" : "=f"(lo), "=f"(hi) : "l"(v));
}

// ---------------- 64-row x 128-col tiled GEMM core (FFMA2 inner loop) ----------------
// 256 threads; thread (tr=tid>>5, tc=tid&31) owns rows tr*8..+7, cols tc*4..+3.
__device__ __forceinline__ void gemm_tile64(
    const float* __restrict__ sIn, int ldi,
    const float* __restrict__ gW, int K,
    float* __restrict__ sW, float acc[8][4])
{
    const int tid = threadIdx.x;
    const int tr  = tid >> 5;
    const int tc  = tid & 31;

    unsigned long long acc2[8][2];
#pragma unroll
    for (int i = 0; i < 8; i++) { acc2[i][0] = 0ull; acc2[i][1] = 0ull; }

    for (int k0 = 0; k0 + 32 <= K; k0 += 32) {
        __syncthreads();   // protect previous use of sW
#pragma unroll
        for (int j = 0; j < 4; j++) {
            int f  = tid + j * 256;
            int rw = f >> 5, cf = f & 31;
            *(float4*)&sW[rw * 128 + cf * 4] =
                __ldg(reinterpret_cast<const float4*>(&gW[(size_t)(k0 + rw) * 128 + cf * 4]));
        }
        __syncthreads();
#pragma unroll
        for (int k4 = 0; k4 < 32; k4 += 4) {
            float4 a[8];
#pragma unroll
            for (int i = 0; i < 8; i++)
                a[i] = *(const float4*)&sIn[(tr * 8 + i) * ldi + k0 + k4];
#pragma unroll
            for (int kk = 0; kk < 4; kk++) {
                const unsigned long long* wp =
                    (const unsigned long long*)&sW[(k4 + kk) * 128 + tc * 4];
                unsigned long long w0 = wp[0], w1 = wp[1];
#pragma unroll
                for (int i = 0; i < 8; i++) {
                    float av = (kk == 0) ? a[i].x : (kk == 1) ? a[i].y
                             : (kk == 2) ? a[i].z : a[i].w;
                    unsigned long long ap = pack2(av);
                    fma2(acc2[i][0], ap, w0);
                    fma2(acc2[i][1], ap, w1);
                }
            }
        }
    }
#pragma unroll
    for (int i = 0; i < 8; i++) {
        unpack2(acc2[i][0], acc[i][0], acc[i][1]);
        unpack2(acc2[i][1], acc[i][2], acc[i][3]);
    }
}

// ---------------- small utility kernels ----------------
__global__ void init_zero_kernel() {
    size_t idx = (size_t)blockIdx.x * 256 + threadIdx.x;
    if (idx < NN)        g_deg[idx]  = 0.0f;
    if (idx < NG * HID)  g_pool[idx] = 0.0f;
    if (idx < NG)        g_cnt[idx]  = 0.0f;
}

__global__ void zero_layer_kernel() {
    size_t idx = (size_t)blockIdx.x * 256 + threadIdx.x;
    if (idx < (size_t)NN * HID) g_magg[idx] = 0.0f;
    if (idx < NN * 3)           g_cagg[idx] = 0.0f;
}

__global__ void deg_kernel(const int* __restrict__ erow) {
    int e = blockIdx.x * 256 + threadIdx.x;
    if (e < NE) atomicAdd(&g_deg[erow[e]], 1.0f);
}

__global__ void cnt_kernel(const int* __restrict__ batch) {
    int i = blockIdx.x * 256 + threadIdx.x;
    if (i < NN) atomicAdd(&g_cnt[batch[i]], 1.0f);
}

__global__ void copy_coord_kernel(const float* __restrict__ c) {
    int i = blockIdx.x * 256 + threadIdx.x;
    if (i < NN * 3) g_coord[i] = c[i];
}

// h = x @ emb_in_w + b   (K=16)
__global__ void embed_kernel(const float* __restrict__ x,
                             const float* __restrict__ W,
                             const float* __restrict__ b) {
    size_t idx = (size_t)blockIdx.x * 256 + threadIdx.x;
    if (idx >= (size_t)NN * HID) return;
    int i = (int)(idx >> 7);
    int c = (int)(idx & 127);
    const float* xr = &x[i * 16];
    float a = b[c];
#pragma unroll
    for (int k = 0; k < 16; k++) a = fmaf(xr[k], W[k * 128 + c], a);
    g_h[idx] = a;
}

// ---------------- per-node precompute: g_hr = h@W1a, g_hc = h@W1b ----------------
#define HPRE_SMEM_F (64 * 132 + 32 * 128)

__global__ void __launch_bounds__(256) hpre_kernel(const float* __restrict__ W1)
{
    extern __shared__ float sm[];
    float* sH = sm;
    float* sW = sH + 64 * 132;

    const int tid = threadIdx.x;
    const int warp = tid >> 5, lane = tid & 31;
    const int n0 = blockIdx.x * 64;

    for (int i = warp; i < 64; i += 8) {
        int node = n0 + i;
        ((float4*)&sH[i * 132])[lane] = (node < NN)
            ? *(const float4*)&g_h[(size_t)node * 128 + lane * 4]
            : make_float4(0.f, 0.f, 0.f, 0.f);
    }

    const int tr = tid >> 5, tc = tid & 31;
    float acc[8][4];

    gemm_tile64(sH, 132, W1, 128, sW, acc);                 // W1a = rows 0..127
#pragma unroll
    for (int i = 0; i < 8; i++) {
        int node = n0 + tr * 8 + i;
        if (node < NN)
            *(float4*)&g_hr[(size_t)node * 128 + tc * 4] =
                make_float4(acc[i][0], acc[i][1], acc[i][2], acc[i][3]);
    }
    __syncthreads();

    gemm_tile64(sH, 132, W1 + 128 * 128, 128, sW, acc);     // W1b = rows 128..255
#pragma unroll
    for (int i = 0; i < 8; i++) {
        int node = n0 + tr * 8 + i;
        if (node < NN)
            *(float4*)&g_hc[(size_t)node * 128 + tc * 4] =
                make_float4(acc[i][0], acc[i][1], acc[i][2], acc[i][3]);
    }
}

// ---------------- edge pipeline (the hot kernel) ----------------
// m1 = silu(hr[row] + hc[col] + radial*w_r + ea*w_e + b1)  -- no K=258 GEMM
#define EDGE_SMEM_F (64 * 132 * 2 + 32 * 128 + 64 * 4 + 3 * 128)

__global__ void __launch_bounds__(256) edge_kernel(
    const int* __restrict__ erow, const int* __restrict__ ecol,
    const float* __restrict__ eattr,
    const float* __restrict__ W1, const float* __restrict__ b1,
    const float* __restrict__ W2, const float* __restrict__ b2,
    const float* __restrict__ Wc1, const float* __restrict__ bc1,
    const float* __restrict__ Wc2)
{
    extern __shared__ float sm[];
    float* sA  = sm;                    // 64 x 132
    float* sB  = sA + 64 * 132;         // 64 x 132
    float* sW  = sB + 64 * 132;         // 32 x 128
    float* sD  = sW + 32 * 128;         // 64 x 4 (diff xyz)
    float* sWR = sD + 64 * 4;           // 128
    float* sWE = sWR + 128;             // 128
    float* sB1 = sWE + 128;             // 128
    __shared__ int sRow[64];

    const int tid = threadIdx.x;
    const int warp = tid >> 5, lane = tid & 31;
    const int e0 = blockIdx.x * 64;

    if (tid < 128) {
        sWR[tid] = __ldg(&W1[256 * 128 + tid]);   // radial row
        sWE[tid] = __ldg(&W1[257 * 128 + tid]);   // edge_attr row
        sB1[tid] = __ldg(&b1[tid]);
    }
    __syncthreads();

    // gather + fused first-layer MLP input
    for (int i = warp; i < 64; i += 8) {
        int e = e0 + i;
        int r = erow[e], c = ecol[e];
        if (lane == 0) sRow[i] = r;
        float d = 0.0f;
        if (lane < 3) { d = g_coord[r * 3 + lane] - g_coord[c * 3 + lane]; sD[i * 4 + lane] = d; }
        __syncwarp();
        float d0 = sD[i * 4], d1 = sD[i * 4 + 1], d2 = sD[i * 4 + 2];
        float radial = d0 * d0 + d1 * d1 + d2 * d2;
        float ea = __ldg(&eattr[e]);
        float4 a = __ldg(reinterpret_cast<const float4*>(&g_hr[(size_t)r * 128 + lane * 4]));
        float4 b = __ldg(reinterpret_cast<const float4*>(&g_hc[(size_t)c * 128 + lane * 4]));
        float4 wr = *(const float4*)&sWR[lane * 4];
        float4 we = *(const float4*)&sWE[lane * 4];
        float4 bb = *(const float4*)&sB1[lane * 4];
        float4 v;
        v.x = silu_f(a.x + b.x + radial * wr.x + ea * we.x + bb.x);
        v.y = silu_f(a.y + b.y + radial * wr.y + ea * we.y + bb.y);
        v.z = silu_f(a.z + b.z + radial * wr.z + ea * we.z + bb.z);
        v.w = silu_f(a.w + b.w + radial * wr.w + ea * we.w + bb.w);
        *(float4*)&sA[i * 132 + lane * 4] = v;
    }

    const int tr = tid >> 5, tc = tid & 31;
    float acc[8][4];

    // GEMM2: m = silu(m1 @ W2 + b2), K = 128 ; scatter magg in epilogue
    gemm_tile64(sA, 132, W2, 128, sW, acc);
    {
        float4 bb = *(const float4*)&b2[tc * 4];
#pragma unroll
        for (int i = 0; i < 8; i++) {
            int node = sRow[tr * 8 + i];
            float4 v;
            v.x = silu_f(acc[i][0] + bb.x);
            v.y = silu_f(acc[i][1] + bb.y);
            v.z = silu_f(acc[i][2] + bb.z);
            v.w = silu_f(acc[i][3] + bb.w);
            *(float4*)&sB[(tr * 8 + i) * 132 + tc * 4] = v;
            float* mg = &g_magg[(size_t)node * 128 + tc * 4];
            atomicAdd(mg + 0, v.x);
            atomicAdd(mg + 1, v.y);
            atomicAdd(mg + 2, v.z);
            atomicAdd(mg + 3, v.w);
        }
    }
    __syncthreads();

    // GEMM3: p = silu(m @ Wc1 + bc1); cw = p @ Wc2 ; scatter coord agg
    gemm_tile64(sB, 132, Wc1, 128, sW, acc);
    {
        float4 bb = *(const float4*)&bc1[tc * 4];
        float4 wc = *(const float4*)&Wc2[tc * 4];
#pragma unroll
        for (int i = 0; i < 8; i++) {
            float p0 = silu_f(acc[i][0] + bb.x);
            float p1 = silu_f(acc[i][1] + bb.y);
            float p2 = silu_f(acc[i][2] + bb.z);
            float p3 = silu_f(acc[i][3] + bb.w);
            float part = p0 * wc.x + p1 * wc.y + p2 * wc.z + p3 * wc.w;
#pragma unroll
            for (int o = 16; o > 0; o >>= 1) part += __shfl_xor_sync(0xffffffffu, part, o);
            if (lane == 0) {
                int row  = tr * 8 + i;
                int node = sRow[row];
                atomicAdd(&g_cagg[node * 3 + 0], sD[row * 4 + 0] * part);
                atomicAdd(&g_cagg[node * 3 + 1], sD[row * 4 + 1] * part);
                atomicAdd(&g_cagg[node * 3 + 2], sD[row * 4 + 2] * part);
            }
        }
    }
}

// ---------------- node update ----------------
#define NODE_SMEM_F (64 * 260 + 64 * 132 + 32 * 128)

__global__ void __launch_bounds__(256) node_kernel(
    const float* __restrict__ W1, const float* __restrict__ b1,
    const float* __restrict__ W2, const float* __restrict__ b2)
{
    extern __shared__ float sm[];
    float* sNF = sm;                 // 64 x 260 : [h | magg]
    float* sA  = sNF + 64 * 260;     // 64 x 132
    float* sW  = sA + 64 * 132;      // 32 x 128

    const int tid = threadIdx.x;
    const int warp = tid >> 5, lane = tid & 31;
    const int n0 = blockIdx.x * 64;

    // coord += cagg / deg
    if (tid < 192) {
        int i = tid / 3, d = tid - i * 3;
        int node = n0 + i;
        if (node < NN)
            g_coord[node * 3 + d] += g_cagg[node * 3 + d] / fmaxf(g_deg[node], 1.0f);
    }

    for (int i = warp; i < 64; i += 8) {
        int node = n0 + i;
        if (node < NN) {
            ((float4*)&sNF[i * 260])[lane] =
                *(const float4*)&g_h[(size_t)node * 128 + lane * 4];
            ((float4*)&sNF[i * 260 + 128])[lane] =
                *(const float4*)&g_magg[(size_t)node * 128 + lane * 4];
        } else {
            ((float4*)&sNF[i * 260])[lane]       = make_float4(0.f, 0.f, 0.f, 0.f);
            ((float4*)&sNF[i * 260 + 128])[lane] = make_float4(0.f, 0.f, 0.f, 0.f);
        }
    }

    const int tr = tid >> 5, tc = tid & 31;
    float acc[8][4];

    gemm_tile64(sNF, 260, W1, 256, sW, acc);
    {
        float4 bb = *(const float4*)&b1[tc * 4];
#pragma unroll
        for (int i = 0; i < 8; i++) {
            float4 v;
            v.x = silu_f(acc[i][0] + bb.x);
            v.y = silu_f(acc[i][1] + bb.y);
            v.z = silu_f(acc[i][2] + bb.z);
            v.w = silu_f(acc[i][3] + bb.w);
            *(float4*)&sA[(tr * 8 + i) * 132 + tc * 4] = v;
        }
    }
    __syncthreads();

    gemm_tile64(sA, 132, W2, 128, sW, acc);
    {
        float4 bb = *(const float4*)&b2[tc * 4];
#pragma unroll
        for (int i = 0; i < 8; i++) {
            int node = n0 + tr * 8 + i;
            if (node < NN) {
                float4 hv = *(const float4*)&sNF[(tr * 8 + i) * 260 + tc * 4];
                float4 o;
                o.x = hv.x + acc[i][0] + bb.x;
                o.y = hv.y + acc[i][1] + bb.y;
                o.z = hv.z + acc[i][2] + bb.z;
                o.w = hv.w + acc[i][3] + bb.w;
                *(float4*)&g_h[(size_t)node * 128 + tc * 4] = o;
            }
        }
    }
}

// ---------------- emb_out + graph pooling ----------------
#define POOL_SMEM_F (64 * 132 + 32 * 128)

__global__ void __launch_bounds__(256) embpool_kernel(
    const int* __restrict__ batch,
    const float* __restrict__ W, const float* __restrict__ b)
{
    extern __shared__ float sm[];
    float* sH = sm;
    float* sW = sH + 64 * 132;

    const int tid = threadIdx.x;
    const int warp = tid >> 5, lane = tid & 31;
    const int n0 = blockIdx.x * 64;

    for (int i = warp; i < 64; i += 8) {
        int node = n0 + i;
        ((float4*)&sH[i * 132])[lane] = (node < NN)
            ? *(const float4*)&g_h[(size_t)node * 128 + lane * 4]
            : make_float4(0.f, 0.f, 0.f, 0.f);
    }

    const int tr = tid >> 5, tc = tid & 31;
    float acc[8][4];
    gemm_tile64(sH, 132, W, 128, sW, acc);

    float4 bb = *(const float4*)&b[tc * 4];
#pragma unroll
    for (int i = 0; i < 8; i++) {
        int node = n0 + tr * 8 + i;
        if (node < NN) {
            int g = batch[node];
            float* pp = &g_pool[g * 128 + tc * 4];
            atomicAdd(pp + 0, acc[i][0] + bb.x);
            atomicAdd(pp + 1, acc[i][1] + bb.y);
            atomicAdd(pp + 2, acc[i][2] + bb.z);
            atomicAdd(pp + 3, acc[i][3] + bb.w);
        }
    }
}

// ---------------- final FC over pooled graph features ----------------
__global__ void final_kernel(const float* __restrict__ fcW,
                             const float* __restrict__ fcB,
                             float* __restrict__ out)
{
    __shared__ float sg[128];
    int c = threadIdx.x;
    for (int g = 0; g < NG; g++) {
        if (c < 128) sg[c] = g_pool[g * 128 + c] / fmaxf(g_cnt[g], 1.0f);
        __syncthreads();
        float a = fcB[c];
#pragma unroll 8
        for (int k = 0; k < 128; k++) a = fmaf(sg[k], fcW[k * 256 + c], a);
        out[g * 256 + c] = a;
        __syncthreads();
    }
}

// ---------------- launch ----------------
extern "C" void kernel_launch(void* const* d_in, const int* in_sizes, int n_in,
                              void* d_out, int out_size)
{
    const float* x        = (const float*)d_in[0];
    const int*   eidx     = (const int*)d_in[1];
    const float* coord_in = (const float*)d_in[2];
    const float* eattr    = (const float*)d_in[3];
    const int*   batch    = (const int*)d_in[4];
    const float* emb_in_w = (const float*)d_in[5];
    const float* emb_in_b = (const float*)d_in[6];
    const float* edge_w1  = (const float*)d_in[7];
    const float* edge_b1  = (const float*)d_in[8];
    const float* edge_w2  = (const float*)d_in[9];
    const float* edge_b2  = (const float*)d_in[10];
    const float* node_w1  = (const float*)d_in[11];
    const float* node_b1  = (const float*)d_in[12];
    const float* node_w2  = (const float*)d_in[13];
    const float* node_b2  = (const float*)d_in[14];
    const float* coord_w1 = (const float*)d_in[15];
    const float* coord_b1 = (const float*)d_in[16];
    const float* coord_w2 = (const float*)d_in[17];
    const float* emb_out_w= (const float*)d_in[18];
    const float* emb_out_b= (const float*)d_in[19];
    const float* fc_w     = (const float*)d_in[20];
    const float* fc_b     = (const float*)d_in[21];
    float* out = (float*)d_out;

    const int* erow = eidx;
    const int* ecol = eidx + NE;

    static bool attr_done = false;
    if (!attr_done) {
        cudaFuncSetAttribute(edge_kernel, cudaFuncAttributeMaxDynamicSharedMemorySize,
                             EDGE_SMEM_F * 4);
        cudaFuncSetAttribute(node_kernel, cudaFuncAttributeMaxDynamicSharedMemorySize,
                             NODE_SMEM_F * 4);
        cudaFuncSetAttribute(embpool_kernel, cudaFuncAttributeMaxDynamicSharedMemorySize,
                             POOL_SMEM_F * 4);
        cudaFuncSetAttribute(hpre_kernel, cudaFuncAttributeMaxDynamicSharedMemorySize,
                             HPRE_SMEM_F * 4);
        attr_done = true;
    }

    init_zero_kernel<<<(NN + 255) / 256, 256>>>();
    deg_kernel<<<(NE + 255) / 256, 256>>>(erow);
    embed_kernel<<<((size_t)NN * HID + 255) / 256, 256>>>(x, emb_in_w, emb_in_b);
    copy_coord_kernel<<<(NN * 3 + 255) / 256, 256>>>(coord_in);

    const int edge_blocks = NE / 64;              // 9375, exact
    const int node_blocks = (NN + 63) / 64;       // 782

    for (int l = 0; l < 3; l++) {
        zero_layer_kernel<<<((size_t)NN * HID + 255) / 256, 256>>>();
        hpre_kernel<<<node_blocks, 256, HPRE_SMEM_F * 4>>>(edge_w1 + (size_t)l * 258 * 128);
        edge_kernel<<<edge_blocks, 256, EDGE_SMEM_F * 4>>>(
            erow, ecol, eattr,
            edge_w1 + (size_t)l * 258 * 128, edge_b1 + l * 128,
            edge_w2 + (size_t)l * 128 * 128, edge_b2 + l * 128,
            coord_w1 + (size_t)l * 128 * 128, coord_b1 + l * 128,
            coord_w2 + (size_t)l * 128);
        node_kernel<<<node_blocks, 256, NODE_SMEM_F * 4>>>(
            node_w1 + (size_t)l * 256 * 128, node_b1 + l * 128,
            node_w2 + (size_t)l * 128 * 128, node_b2 + l * 128);
    }

    cnt_kernel<<<(NN + 255) / 256, 256>>>(batch);
    embpool_kernel<<<node_blocks, 256, POOL_SMEM_F * 4>>>(batch, emb_out_w, emb_out_b);
    final_kernel<<<1, 256>>>(fc_w, fc_b, out);
}